// round 10
// baseline (speedup 1.0000x reference)
#include <cuda_runtime.h>
#include <cstdint>

#define Bb 2
#define Cc 66
#define Tt 32
#define Nn 512
#define TNc (Tt*Nn)          // 16384
#define BTNc (Bb*TNc)        // 32768
#define Ll 2
#define Kn 16

// ---------------- device scratch (no cudaMalloc allowed) ----------------
static __device__ float g_proj[33554432];     // [BTN][1024]  (134 MB)
static __device__ int   g_nid[BTNc * Kn];     // neighbor global point ids
static __device__ float g_wcombT[64 * 1024];  // [c][row] transposed combined weights
static __device__ float g_bias[1024];
static __device__ float g_wpos[2 * 256 * 4];  // [l][row(252 pad 256)][4]

// Per-point row layout (stride 1024):
//   l*512 + 0   ..127 : center q|k (+bias)     l*512+128..251 : center v (+bias)
//   l*512 + 256 ..383 : neighbor q|k           l*512+384..507 : neighbor v

// ---------------- K0: weight prep ----------------
__global__ __launch_bounds__(256) void prep_kernel(
        const float* __restrict__ Wqk, const float* __restrict__ bqk,
        const float* __restrict__ Wv,  const float* __restrict__ bv) {
    int i = blockIdx.x * blockDim.x + threadIdx.x;   // 0 .. 65535
    {
        int c = i >> 10, r = i & 1023;
        int l = r >> 9, within = r & 511, typ = within >> 8, o = within & 255;
        float w = 0.f;
        if (o < 252 && c < 62) {
            int col = (typ == 0 ? 4 : 66) + c;
            if (o < 128) w = Wqk[(l * 128 + o) * 128 + col];
            else         w = Wv[(l * 124 + (o - 128)) * 128 + col];
        }
        g_wcombT[c * 1024 + r] = w;
    }
    if (i < 1024) {
        int r = i, l = r >> 9, within = r & 511, typ = within >> 8, o = within & 255;
        float bb = 0.f;
        if (typ == 0 && o < 252) bb = (o < 128) ? bqk[l * 128 + o] : bv[l * 124 + (o - 128)];
        g_bias[r] = bb;
    }
    if (i < 2048) {
        int l = i >> 10, rem = i & 1023, o = rem >> 2, j = rem & 3;
        float w = 0.f;
        if (o < 128)      w = Wqk[(l * 128 + o) * 128 + j];
        else if (o < 252) w = Wv[(l * 124 + (o - 128)) * 128 + j];
        g_wpos[i] = w;
    }
}

// ---------------- K1: kNN v3 (warp-per-point, lane-distributed sorted top-16) ----------------
__global__ __launch_bounds__(256) void knn_kernel(const float* __restrict__ x) {
    int blk = blockIdx.x;            // 0..4095
    int bt = blk >> 6, seg = blk & 63;
    int b = bt / Tt, t = bt % Tt;
    int tid = threadIdx.x, wid = tid >> 5, lane = tid & 31;
    int n = seg * 8 + wid;

    __shared__ __align__(16) float4 pool[1536];   // 24 KB
    const float* xb = x + (size_t)b * Cc * TNc;
    for (int idx = tid; idx < 1536; idx += 256) {
        int s = idx >> 9, j = idx & 511;
        int tp = t - 1 + s; tp = tp < 0 ? 0 : (tp > Tt - 1 ? Tt - 1 : tp);
        float cx = xb[0 * TNc + tp * Nn + j];
        float cy = xb[1 * TNc + tp * Nn + j];
        float cz = xb[2 * TNc + tp * Nn + j];
        float cc = fmaf(cx, cx, fmaf(cy, cy, cz * cz));
        pool[idx] = make_float4(cx, cy, cz, cc);
    }
    __syncthreads();

    float px = xb[0 * TNc + t * Nn + n];
    float py = xb[1 * TNc + t * Nn + n];
    float pz = xb[2 * TNc + t * Nn + n];

    unsigned long long S = ~0ull;
    unsigned long long thresh = ~0ull;   // 16th best (lane 15's S)

    for (int c0 = 0; c0 < 1536; c0 += 32) {
        int j = c0 + lane;
        float4 cd = pool[j];
        float e = fmaf(-2.f, fmaf(px, cd.x, fmaf(py, cd.y, pz * cd.z)), cd.w);
        unsigned bits = __float_as_uint(e);
        unsigned u = bits ^ ((unsigned)((int)bits >> 31) | 0x80000000u);
        unsigned long long kk = ((unsigned long long)u << 32) | (unsigned)j;

        unsigned mask = __ballot_sync(0xFFFFFFFFu, kk < thresh);
        while (mask) {
            int src = __ffs(mask) - 1;          // ascending j => exact tie order
            mask &= mask - 1;
            unsigned long long val = __shfl_sync(0xFFFFFFFFu, kk, src);
            if (val < thresh) {
                unsigned long long up = __shfl_up_sync(0xFFFFFFFFu, S, 1);
                if (lane < 16 && val < S)
                    S = (lane > 0 && val < up) ? up : val;
                thresh = __shfl_sync(0xFFFFFFFFu, S, 15);
            }
        }
    }

    if (lane < 16) {
        unsigned pj = (unsigned)(S & 0xFFFFFFFFu);
        int s = (int)(pj >> 9), jn = (int)(pj & 511u);
        int tp = t - 1 + s; tp = tp < 0 ? 0 : (tp > Tt - 1 ? Tt - 1 : tp);
        g_nid[(bt * Nn + n) * Kn + lane] = (b * Tt + tp) * Nn + jn;
    }
}

// ---------------- K2: projection GEMM (1008x62) @ (62 x 32768) ----------------
__global__ __launch_bounds__(256) void proj_kernel(const float* __restrict__ x) {
    __shared__ __align__(16) float Xs[62][128];
    int p0 = blockIdx.x * 128;
    int b = p0 / TNc, rem0 = p0 % TNc;
    const float* xb = x + ((size_t)b * Cc + 4) * TNc + rem0;
    for (int idx = threadIdx.x; idx < 62 * 128; idx += 256) {
        int c = idx >> 7, pp = idx & 127;
        Xs[c][pp] = xb[(size_t)c * TNc + pp];
    }
    __syncthreads();

    int tx = threadIdx.x & 31, ty = threadIdx.x >> 5;
    float* outBase = g_proj + (size_t)(p0 + tx * 4) * 1024;

    for (int chunk = 0; chunk < 16; chunk++) {
        int r0 = ty * 128 + chunk * 8;
        float acc[8][4];
#pragma unroll
        for (int rr = 0; rr < 8; rr++) {
            float bb = g_bias[r0 + rr];
#pragma unroll
            for (int pp = 0; pp < 4; pp++) acc[rr][pp] = bb;
        }
#pragma unroll 2
        for (int c = 0; c < 62; c++) {
            const float4 xv = *(const float4*)&Xs[c][tx * 4];
            const float4 wa = *(const float4*)&g_wcombT[c * 1024 + r0];
            const float4 wb = *(const float4*)&g_wcombT[c * 1024 + r0 + 4];
            float wv[8] = {wa.x, wa.y, wa.z, wa.w, wb.x, wb.y, wb.z, wb.w};
            float xvv[4] = {xv.x, xv.y, xv.z, xv.w};
#pragma unroll
            for (int rr = 0; rr < 8; rr++)
#pragma unroll
                for (int pp = 0; pp < 4; pp++)
                    acc[rr][pp] = fmaf(wv[rr], xvv[pp], acc[rr][pp]);
        }
#pragma unroll
        for (int pp = 0; pp < 4; pp++) {
            float* dst = outBase + (size_t)pp * 1024 + r0;
            *(float4*)dst       = make_float4(acc[0][pp], acc[1][pp], acc[2][pp], acc[3][pp]);
            *(float4*)(dst + 4) = make_float4(acc[4][pp], acc[5][pp], acc[6][pp], acc[7][pp]);
        }
    }
}

// ---------------- K3: attention v6b (4-pt batched phases, 2x2 energy tiling) ----------------
// dynamic smem floats:
#define OFF_QK    0                     // [4][16][132]  = 8448
#define OFF_ES    8448                  // [4][16*17]    = 1088
#define OFF_DELTA 9536                  // [16][16] f4   = 1024
#define OFF_NID   10560                 // [16][16] int  = 256
#define OFF_WPOS  10816                 // 2048
#define OFF_OUTS  12864                 // [16][128]     = 2048
#define SMEM_FLOATS 14912
#define SMEM_BYTES  (SMEM_FLOATS * 4)

__global__ __launch_bounds__(256, 3) void attn_kernel(const float* __restrict__ x,
                                                      float* __restrict__ out) {
    extern __shared__ __align__(16) float sm[];
    float*  qk4     = sm + OFF_QK;
    float*  eS4     = sm + OFF_ES;
    float4* delta16 = (float4*)(sm + OFF_DELTA);   // [16 pts][16]
    int*    nid16   = (int*)(sm + OFF_NID);        // [16 pts][16]
    float*  wposS   = sm + OFF_WPOS;
    float*  outS    = sm + OFF_OUTS;

    int tid = threadIdx.x;
    int lane = tid & 31;
    int p0 = blockIdx.x * 16;
    int b = p0 / TNc, rem0 = p0 % TNc;

    for (int i = tid; i < 2048; i += 256) wposS[i] = g_wpos[i];
    // ph0: nid + delta for all 16 points (256 = 16 pts x 16 nbrs), layer-independent
    {
        int PT = tid >> 4, i = tid & 15;
        int p = p0 + PT;
        int gg = g_nid[p * Kn + i];
        nid16[PT * 16 + i] = gg;
        int grem = gg - b * TNc;
        float4 d;
        d.x = x[((size_t)b * Cc + 0) * TNc + rem0 + PT] - x[((size_t)b * Cc + 0) * TNc + grem];
        d.y = x[((size_t)b * Cc + 1) * TNc + rem0 + PT] - x[((size_t)b * Cc + 1) * TNc + grem];
        d.z = x[((size_t)b * Cc + 2) * TNc + rem0 + PT] - x[((size_t)b * Cc + 2) * TNc + grem];
        d.w = x[((size_t)b * Cc + 3) * TNc + rem0 + PT] - x[((size_t)b * Cc + 3) * TNc + grem];
        delta16[PT * 16 + i] = d;
    }
    if (tid < 64) {
        int PT = tid >> 2, cc = tid & 3;
        outS[PT * 128 + cc] = x[((size_t)b * Cc + cc) * TNc + rem0 + PT];
    }
    __syncthreads();

    for (int l = 0; l < Ll; l++) {
        for (int bb = 0; bb < 4; bb++) {
            // ---- ph1: assemble q|k for 4 points (2 sub-iters x 2 pts) ----
            {
                int ch = tid & 127;
                float4 w4 = *(const float4*)&wposS[l * 1024 + ch * 4];
#pragma unroll
                for (int sub = 0; sub < 2; sub++) {
                    int ptl = sub * 2 + (tid >> 7);
                    int PT = bb * 4 + ptl;
                    int p = p0 + PT;
                    float base = __ldg(&g_proj[(size_t)p * 1024 + l * 512 + ch]);
                    float* dst = qk4 + ptl * 2112 + ch;
                    const int*    nid = nid16 + PT * 16;
                    const float4* del = delta16 + PT * 16;
#pragma unroll
                    for (int i = 0; i < 16; i++) {
                        float4 dd = del[i];
                        float nbv = __ldg(&g_proj[(size_t)nid[i] * 1024 + l * 512 + 256 + ch]);
                        dst[i * 132] = nbv + base + w4.x * dd.x + w4.y * dd.y
                                       + w4.z * dd.z + w4.w * dd.w;
                    }
                }
            }
            __syncthreads();   // bar1

            // ---- ph2: v-prefetch + energy (2x2 tiling) ----
            int pt = tid >> 6, r = tid & 63;
            int PT = bb * 4 + pt;
            const int* nid = nid16 + PT * 16;
            int chA = r;
            int chB = 64 + (r < 60 ? r : 0);   // clamped: all lanes do valid work
            float vA[16], vB[16];
            {
#pragma unroll
                for (int i = 0; i < 16; i++)
                    vA[i] = __ldg(&g_proj[(size_t)nid[i] * 1024 + l * 512 + 384 + chA]);
#pragma unroll
                for (int i = 0; i < 16; i++)
                    vB[i] = __ldg(&g_proj[(size_t)nid[i] * 1024 + l * 512 + 384 + chB]);

                int i0 = r >> 3, j0 = r & 7;
                const float* Q = qk4 + pt * 2112;
                const float* qa = Q + i0 * 132;
                const float* qb = Q + (i0 + 8) * 132;
                const float* ka = Q + j0 * 132 + 64;
                const float* kb = Q + (j0 + 8) * 132 + 64;
                float e00 = 0.f, e01 = 0.f, e10 = 0.f, e11 = 0.f;
#pragma unroll
                for (int c4 = 0; c4 < 16; c4++) {
                    float4 a4 = *(const float4*)(qa + c4 * 4);
                    float4 b4 = *(const float4*)(qb + c4 * 4);
                    float4 c4a = *(const float4*)(ka + c4 * 4);
                    float4 c4b = *(const float4*)(kb + c4 * 4);
                    e00 = fmaf(a4.x, c4a.x, e00); e00 = fmaf(a4.y, c4a.y, e00);
                    e00 = fmaf(a4.z, c4a.z, e00); e00 = fmaf(a4.w, c4a.w, e00);
                    e01 = fmaf(a4.x, c4b.x, e01); e01 = fmaf(a4.y, c4b.y, e01);
                    e01 = fmaf(a4.z, c4b.z, e01); e01 = fmaf(a4.w, c4b.w, e01);
                    e10 = fmaf(b4.x, c4a.x, e10); e10 = fmaf(b4.y, c4a.y, e10);
                    e10 = fmaf(b4.z, c4a.z, e10); e10 = fmaf(b4.w, c4a.w, e10);
                    e11 = fmaf(b4.x, c4b.x, e11); e11 = fmaf(b4.y, c4b.y, e11);
                    e11 = fmaf(b4.z, c4b.z, e11); e11 = fmaf(b4.w, c4b.w, e11);
                }
                float* es = eS4 + pt * 272;
                es[i0 * 17 + j0]            = e00 * 0.125f;
                es[i0 * 17 + j0 + 8]        = e01 * 0.125f;
                es[(i0 + 8) * 17 + j0]      = e10 * 0.125f;
                es[(i0 + 8) * 17 + j0 + 8]  = e11 * 0.125f;
            }
            __syncthreads();   // bar2

            // ---- ph3+4: in-warp softmax + out. ALL shuffles convergent;
            //      only the final chB store is predicated. ----
            {
                const float* es = eS4 + pt * 272;
                float af = 0.f;
                float4 dd = make_float4(0.f, 0.f, 0.f, 0.f);
                if (lane < 16) {
                    const float* er = es + lane * 17;
                    float m = -1e30f;
#pragma unroll
                    for (int j = 0; j < 16; j++) m = fmaxf(m, er[j]);
                    float sum = 0.f;
#pragma unroll
                    for (int j = 0; j < 16; j++) sum += __expf(er[j] - m);
                    af = __expf(er[0] - m) / sum;
                    dd = delta16[PT * 16 + lane];
                }
                float s0 = af, dx = af * dd.x, dy = af * dd.y, dz = af * dd.z, dw = af * dd.w;
#pragma unroll
                for (int off = 16; off > 0; off >>= 1) {
                    s0 += __shfl_xor_sync(0xFFFFFFFFu, s0, off);
                    dx += __shfl_xor_sync(0xFFFFFFFFu, dx, off);
                    dy += __shfl_xor_sync(0xFFFFFFFFu, dy, off);
                    dz += __shfl_xor_sync(0xFFFFFFFFu, dz, off);
                    dw += __shfl_xor_sync(0xFFFFFFFFu, dw, off);
                }
                int p = p0 + PT;
                const float* rowC = g_proj + (size_t)p * 1024 + l * 512;

                float4 wvA = *(const float4*)&wposS[l * 1024 + (128 + chA) * 4];
                float accA = s0 * __ldg(&rowC[128 + chA])
                           + wvA.x * dx + wvA.y * dy + wvA.z * dz + wvA.w * dw;
                float4 wvB = *(const float4*)&wposS[l * 1024 + (128 + chB) * 4];
                float accB = s0 * __ldg(&rowC[128 + chB])
                           + wvB.x * dx + wvB.y * dy + wvB.z * dz + wvB.w * dw;
#pragma unroll
                for (int i = 0; i < 16; i++) {
                    float afi = __shfl_sync(0xFFFFFFFFu, af, i);  // convergent
                    accA = fmaf(afi, vA[i], accA);
                    accB = fmaf(afi, vB[i], accB);
                }
                outS[PT * 128 + 4 + chA] = accA;
                if (r < 60) outS[PT * 128 + 4 + chB] = accB;
            }
        }
        // flush this layer's 16 points
        __syncthreads();
        for (int idx = tid; idx < 2048; idx += 256) {
            int c = idx >> 4, PT = idx & 15;
            out[((size_t)(l * Bb + b) * 128 + c) * TNc + rem0 + PT] = outS[PT * 128 + c];
        }
        __syncthreads();
    }
}

// ---------------- launch ----------------
extern "C" void kernel_launch(void* const* d_in, const int* in_sizes, int n_in,
                              void* d_out, int out_size) {
    const float* x   = (const float*)d_in[0];
    const float* Wqk = (const float*)d_in[1];
    const float* bqk = (const float*)d_in[2];
    const float* Wv  = (const float*)d_in[3];
    const float* bv  = (const float*)d_in[4];
    float* out = (float*)d_out;

    cudaFuncSetAttribute(attn_kernel, cudaFuncAttributeMaxDynamicSharedMemorySize, SMEM_BYTES);

    prep_kernel<<<256, 256>>>(Wqk, bqk, Wv, bv);
    knn_kernel<<<4096, 256>>>(x);
    proj_kernel<<<BTNc / 128, 256>>>(x);
    attn_kernel<<<BTNc / 16, 256, SMEM_BYTES>>>(x, out);
}

// round 12
// speedup vs baseline: 1.0270x; 1.0270x over previous
#include <cuda_runtime.h>
#include <mma.h>
#include <cstdint>

using namespace nvcuda;

#define Bb 2
#define Cc 66
#define Tt 32
#define Nn 512
#define TNc (Tt*Nn)          // 16384
#define BTNc (Bb*TNc)        // 32768
#define Ll 2
#define Kn 16

// ---------------- device scratch (no cudaMalloc allowed) ----------------
static __device__ float g_proj[33554432];     // [BTN][1024]  (134 MB)
static __device__ int   g_nid[BTNc * Kn];     // neighbor global point ids
static __device__ float g_wtf_hi[65536];      // [1024 rows][64 k]  tf32 hi
static __device__ float g_wtf_lo[65536];      // [1024 rows][64 k]  tf32 lo
static __device__ float g_bias[1024];
static __device__ float g_wpos[2 * 256 * 4];  // [l][row(252 pad 256)][4]

// Per-point row layout (stride 1024):
//   l*512 + 0   ..127 : center q|k (+bias)     l*512+128..251 : center v (+bias)
//   l*512 + 256 ..383 : neighbor q|k           l*512+384..507 : neighbor v

__device__ __forceinline__ float to_tf32(float v) {
    unsigned u;
    asm("cvt.rna.tf32.f32 %0, %1;" : "=r"(u) : "f"(v));
    return __uint_as_float(u);
}

// ---------------- K0: weight prep ----------------
__global__ __launch_bounds__(256) void prep_kernel(
        const float* __restrict__ Wqk, const float* __restrict__ bqk,
        const float* __restrict__ Wv,  const float* __restrict__ bv) {
    int i = blockIdx.x * blockDim.x + threadIdx.x;   // 0 .. 65535
    {
        int r = i >> 6, c = i & 63;
        int l = r >> 9, within = r & 511, typ = within >> 8, o = within & 255;
        float w = 0.f;
        if (o < 252 && c < 62) {
            int col = (typ == 0 ? 4 : 66) + c;
            if (o < 128) w = Wqk[(l * 128 + o) * 128 + col];
            else         w = Wv[(l * 124 + (o - 128)) * 128 + col];
        }
        float hi = to_tf32(w);
        float lo = to_tf32(w - hi);
        g_wtf_hi[r * 64 + c] = hi;
        g_wtf_lo[r * 64 + c] = lo;
    }
    if (i < 1024) {
        int r = i, l = r >> 9, within = r & 511, typ = within >> 8, o = within & 255;
        float bb = 0.f;
        if (typ == 0 && o < 252) bb = (o < 128) ? bqk[l * 128 + o] : bv[l * 124 + (o - 128)];
        g_bias[r] = bb;
    }
    if (i < 2048) {
        int l = i >> 10, rem = i & 1023, o = rem >> 2, j = rem & 3;
        float w = 0.f;
        if (o < 128)      w = Wqk[(l * 128 + o) * 128 + j];
        else if (o < 252) w = Wv[(l * 124 + (o - 128)) * 128 + j];
        g_wpos[i] = w;
    }
}

// ---------------- K1: kNN v3 (warp-per-point, lane-distributed sorted top-16) ----------------
__global__ __launch_bounds__(256) void knn_kernel(const float* __restrict__ x) {
    int blk = blockIdx.x;            // 0..4095
    int bt = blk >> 6, seg = blk & 63;
    int b = bt / Tt, t = bt % Tt;
    int tid = threadIdx.x, wid = tid >> 5, lane = tid & 31;
    int n = seg * 8 + wid;

    __shared__ __align__(16) float4 pool[1536];   // 24 KB
    const float* xb = x + (size_t)b * Cc * TNc;
    for (int idx = tid; idx < 1536; idx += 256) {
        int s = idx >> 9, j = idx & 511;
        int tp = t - 1 + s; tp = tp < 0 ? 0 : (tp > Tt - 1 ? Tt - 1 : tp);
        float cx = xb[0 * TNc + tp * Nn + j];
        float cy = xb[1 * TNc + tp * Nn + j];
        float cz = xb[2 * TNc + tp * Nn + j];
        float cc = fmaf(cx, cx, fmaf(cy, cy, cz * cz));
        pool[idx] = make_float4(cx, cy, cz, cc);
    }
    __syncthreads();

    float px = xb[0 * TNc + t * Nn + n];
    float py = xb[1 * TNc + t * Nn + n];
    float pz = xb[2 * TNc + t * Nn + n];

    unsigned long long S = ~0ull;
    unsigned long long thresh = ~0ull;   // 16th best (lane 15's S)

    for (int c0 = 0; c0 < 1536; c0 += 32) {
        int j = c0 + lane;
        float4 cd = pool[j];
        float e = fmaf(-2.f, fmaf(px, cd.x, fmaf(py, cd.y, pz * cd.z)), cd.w);
        unsigned bits = __float_as_uint(e);
        unsigned u = bits ^ ((unsigned)((int)bits >> 31) | 0x80000000u);
        unsigned long long kk = ((unsigned long long)u << 32) | (unsigned)j;

        unsigned mask = __ballot_sync(0xFFFFFFFFu, kk < thresh);
        while (mask) {
            int src = __ffs(mask) - 1;          // ascending j => exact tie order
            mask &= mask - 1;
            unsigned long long val = __shfl_sync(0xFFFFFFFFu, kk, src);
            if (val < thresh) {
                unsigned long long up = __shfl_up_sync(0xFFFFFFFFu, S, 1);
                if (lane < 16 && val < S)
                    S = (lane > 0 && val < up) ? up : val;
                thresh = __shfl_sync(0xFFFFFFFFu, S, 15);
            }
        }
    }

    if (lane < 16) {
        unsigned pj = (unsigned)(S & 0xFFFFFFFFu);
        int s = (int)(pj >> 9), jn = (int)(pj & 511u);
        int tp = t - 1 + s; tp = tp < 0 ? 0 : (tp > Tt - 1 ? Tt - 1 : tp);
        g_nid[(bt * Nn + n) * Kn + lane] = (b * Tt + tp) * Nn + jn;
    }
}

// ---------------- K2: projection GEMM via tf32 tensor cores (3-pass split) ----------------
// C[1024 rows][128 pts] per block; A = weights (hi/lo in regs), B = x tile (hi/lo in smem).
// dynamic smem floats: Xhi[64][128]=8192 | Xlo[64][128]=8192 | Cst[8][256]=2048 | bias 1024
#define PROJ_SM_FLOATS (8192 + 8192 + 2048 + 1024)
#define PROJ_SM_BYTES  (PROJ_SM_FLOATS * 4)

__global__ __launch_bounds__(256) void proj_kernel(const float* __restrict__ x) {
    extern __shared__ __align__(32) float psm[];
    float* Xhi   = psm;
    float* Xlo   = psm + 8192;
    float* Cst   = psm + 16384;          // [8 warps][256]
    float* biasS = psm + 18432;          // [1024]

    int tid = threadIdx.x, wid = tid >> 5, lane = tid & 31;
    int p0 = blockIdx.x * 128;
    int b = p0 / TNc, rem0 = p0 % TNc;
    const float* xb = x + ((size_t)b * Cc + 4) * TNc + rem0;

    for (int i = tid; i < 8192; i += 256) {
        int c = i >> 7, pt = i & 127;
        float v = (c < 62) ? xb[(size_t)c * TNc + pt] : 0.f;
        float hi = to_tf32(v);
        Xhi[i] = hi;
        Xlo[i] = to_tf32(v - hi);
    }
    for (int i = tid; i < 1024; i += 256) biasS[i] = g_bias[i];
    __syncthreads();

    float* myC = Cst + wid * 256;
    int pt = lane >> 1, rb = (lane & 1) * 8;

    for (int round = 0; round < 8; round++) {
        int rt = round * 8 + wid;          // row tile: rows rt*16 .. rt*16+15
        wmma::fragment<wmma::matrix_a, 16, 16, 8, wmma::precision::tf32, wmma::row_major> Ahi[8], Alo[8];
#pragma unroll
        for (int k8 = 0; k8 < 8; k8++) {
            wmma::load_matrix_sync(Ahi[k8], g_wtf_hi + rt * 1024 + k8 * 8, 64);
            wmma::load_matrix_sync(Alo[k8], g_wtf_lo + rt * 1024 + k8 * 8, 64);
        }
#pragma unroll
        for (int ct = 0; ct < 8; ct++) {
            wmma::fragment<wmma::accumulator, 16, 16, 8, float> C;
            wmma::fill_fragment(C, 0.f);
#pragma unroll
            for (int k8 = 0; k8 < 8; k8++) {
                wmma::fragment<wmma::matrix_b, 16, 16, 8, wmma::precision::tf32, wmma::row_major> Bhi, Blo;
                wmma::load_matrix_sync(Bhi, Xhi + k8 * 8 * 128 + ct * 16, 128);
                wmma::load_matrix_sync(Blo, Xlo + k8 * 8 * 128 + ct * 16, 128);
                wmma::mma_sync(C, Ahi[k8], Bhi, C);
                wmma::mma_sync(C, Ahi[k8], Blo, C);
                wmma::mma_sync(C, Alo[k8], Bhi, C);
            }
            wmma::store_matrix_sync(myC, C, 16, wmma::mem_row_major);
            __syncwarp();
            // copy 16x16 tile to g_proj (transposed, +bias): lane -> (pt, 8 rows)
            int rowbase = rt * 16 + rb;
            float vals[8];
#pragma unroll
            for (int ri = 0; ri < 8; ri++)
                vals[ri] = myC[(rb + ri) * 16 + pt] + biasS[rowbase + ri];
            float* dst = g_proj + (size_t)(p0 + ct * 16 + pt) * 1024 + rowbase;
            *(float4*)dst       = make_float4(vals[0], vals[1], vals[2], vals[3]);
            *(float4*)(dst + 4) = make_float4(vals[4], vals[5], vals[6], vals[7]);
            __syncwarp();
        }
    }
}

// ---------------- K3: attention v5 (R8 build, proven 471us) ----------------
#define GSTR 3040
#define SM_FLOATS (2 * GSTR + 2048 + 2048)

__device__ __forceinline__ void bar_group(int gi) {
    asm volatile("bar.sync %0, 128;" :: "r"(gi + 1) : "memory");
}

__global__ __launch_bounds__(256, 4) void attn_kernel(const float* __restrict__ x,
                                                      float* __restrict__ out) {
    __shared__ __align__(16) float sm[SM_FLOATS];
    int tid = threadIdx.x;
    int gi = tid >> 7, gt = tid & 127;
    int lane = gt & 31;

    float*  qk      = sm + gi * GSTR;                  // [16][132]
    float*  eS      = sm + gi * GSTR + 2112;           // [16][17]
    float4* delta8  = (float4*)(sm + gi * GSTR + 2384); // [8 pts][16]
    int*    nid8    = (int*)(sm + gi * GSTR + 2896);    // [8 pts][16]
    float*  wposS   = sm + 2 * GSTR;
    float*  outS    = sm + 2 * GSTR + 2048;            // [16][128] (one layer)

    int p0 = blockIdx.x * 16;
    int b = p0 / TNc, rem0 = p0 % TNc;

    for (int i = tid; i < 2048; i += 256) wposS[i] = g_wpos[i];
    {
        int it = gt >> 4, i = gt & 15;
        int pt = gi * 8 + it;
        int p = p0 + pt;
        int gg = g_nid[p * Kn + i];
        nid8[it * 16 + i] = gg;
        int grem = gg - b * TNc;
        float4 d;
        d.x = x[((size_t)b * Cc + 0) * TNc + rem0 + pt] - x[((size_t)b * Cc + 0) * TNc + grem];
        d.y = x[((size_t)b * Cc + 1) * TNc + rem0 + pt] - x[((size_t)b * Cc + 1) * TNc + grem];
        d.z = x[((size_t)b * Cc + 2) * TNc + rem0 + pt] - x[((size_t)b * Cc + 2) * TNc + grem];
        d.w = x[((size_t)b * Cc + 3) * TNc + rem0 + pt] - x[((size_t)b * Cc + 3) * TNc + grem];
        delta8[it * 16 + i] = d;
    }
    if (tid < 64) {
        int pt = tid >> 2, cc = tid & 3;
        outS[pt * 128 + cc] = x[((size_t)b * Cc + cc) * TNc + rem0 + pt];
    }
    __syncthreads();

    int cch = gt < 124 ? gt : 0;   // clamped v-channel for tail lanes

    for (int l = 0; l < Ll; l++) {
        for (int it = 0; it < 8; it++) {
            int pt = gi * 8 + it;
            int p = p0 + pt;
            const float*  rowC   = g_proj + (size_t)p * 1024 + l * 512;
            const int*    nidS   = nid8 + it * 16;
            const float4* deltaS = delta8 + it * 16;

            // ph1: assemble q,k (i-major). thread = channel c = gt
            {
                float4 w4 = *(const float4*)&wposS[l * 1024 + gt * 4];
                float base = rowC[gt];
#pragma unroll
                for (int i = 0; i < 16; i++) {
                    float4 dd = deltaS[i];
                    float nbv = __ldg(&g_proj[(size_t)nidS[i] * 1024 + l * 512 + 256 + gt]);
                    qk[i * 132 + gt] = nbv + base + w4.x * dd.x + w4.y * dd.y
                                       + w4.z * dd.z + w4.w * dd.w;
                }
            }
            bar_group(gi);

            // ph2: prefetch v-gather into regs, then energy
            float vreg[16];
            {
#pragma unroll
                for (int i = 0; i < 16; i++)
                    vreg[i] = __ldg(&g_proj[(size_t)nidS[i] * 1024 + l * 512 + 384 + cch]);

                int i = gt >> 3, jh = gt & 7;
                const float* qb = qk + i * 132;
                const float* k0 = qk + jh * 132 + 64;
                const float* k1 = qk + (jh + 8) * 132 + 64;
                float a0 = 0.f, a1 = 0.f;
#pragma unroll
                for (int c4 = 0; c4 < 16; c4++) {
                    float4 q4 = *(const float4*)(qb + c4 * 4);
                    float4 ka = *(const float4*)(k0 + c4 * 4);
                    float4 kb = *(const float4*)(k1 + c4 * 4);
                    a0 = fmaf(q4.x, ka.x, a0); a0 = fmaf(q4.y, ka.y, a0);
                    a0 = fmaf(q4.z, ka.z, a0); a0 = fmaf(q4.w, ka.w, a0);
                    a1 = fmaf(q4.x, kb.x, a1); a1 = fmaf(q4.y, kb.y, a1);
                    a1 = fmaf(q4.z, kb.z, a1); a1 = fmaf(q4.w, kb.w, a1);
                }
                eS[i * 17 + jh] = a0 * 0.125f;
                eS[i * 17 + jh + 8] = a1 * 0.125f;
            }
            bar_group(gi);

            // ph3+4: in-warp redundant softmax + out
            {
                float af = 0.f;
                float4 dd = make_float4(0.f, 0.f, 0.f, 0.f);
                if (lane < 16) {
                    const float* er = eS + lane * 17;
                    float m = -1e30f;
#pragma unroll
                    for (int j = 0; j < 16; j++) m = fmaxf(m, er[j]);
                    float sum = 0.f;
#pragma unroll
                    for (int j = 0; j < 16; j++) sum += __expf(er[j] - m);
                    af = __expf(er[0] - m) / sum;
                    dd = deltaS[lane];
                }
                float s0 = af, dx = af * dd.x, dy = af * dd.y, dz = af * dd.z, dw = af * dd.w;
#pragma unroll
                for (int off = 16; off > 0; off >>= 1) {
                    s0 += __shfl_xor_sync(0xFFFFFFFFu, s0, off);
                    dx += __shfl_xor_sync(0xFFFFFFFFu, dx, off);
                    dy += __shfl_xor_sync(0xFFFFFFFFu, dy, off);
                    dz += __shfl_xor_sync(0xFFFFFFFFu, dz, off);
                    dw += __shfl_xor_sync(0xFFFFFFFFu, dw, off);
                }
                float4 wv = *(const float4*)&wposS[l * 1024 + (128 + cch) * 4];
                float acc = s0 * rowC[128 + cch]
                          + wv.x * dx + wv.y * dy + wv.z * dz + wv.w * dw;
#pragma unroll
                for (int i = 0; i < 16; i++) {
                    float afi = __shfl_sync(0xFFFFFFFFu, af, i);
                    acc = fmaf(afi, vreg[i], acc);
                }
                if (gt < 124) outS[pt * 128 + 4 + gt] = acc;
            }
            bar_group(gi);   // WAR guard on qk/eS before next assemble
        }
        __syncthreads();
        for (int idx = tid; idx < 2048; idx += 256) {
            int c = idx >> 4, pt = idx & 15;
            out[((size_t)(l * Bb + b) * 128 + c) * TNc + rem0 + pt] = outS[pt * 128 + c];
        }
        __syncthreads();
    }
}

// ---------------- launch ----------------
extern "C" void kernel_launch(void* const* d_in, const int* in_sizes, int n_in,
                              void* d_out, int out_size) {
    const float* x   = (const float*)d_in[0];
    const float* Wqk = (const float*)d_in[1];
    const float* bqk = (const float*)d_in[2];
    const float* Wv  = (const float*)d_in[3];
    const float* bv  = (const float*)d_in[4];
    float* out = (float*)d_out;

    cudaFuncSetAttribute(proj_kernel, cudaFuncAttributeMaxDynamicSharedMemorySize, PROJ_SM_BYTES);

    prep_kernel<<<256, 256>>>(Wqk, bqk, Wv, bv);
    knn_kernel<<<4096, 256>>>(x);
    proj_kernel<<<BTNc / 128, 256, PROJ_SM_BYTES>>>(x);
    attn_kernel<<<BTNc / 16, 256>>>(x, out);
}